// round 3
// baseline (speedup 1.0000x reference)
#include <cuda_runtime.h>
#include <cuda_bf16.h>
#include <math.h>
#include <stdint.h>

// ---------------------------------------------------------------------------
// VQ-VAE VectorQuantizer forward — bf16 mma.sync candidate filter + exact
// fp32 rescore (base sm_100 ISA: ldmatrix + mma.sync, no tcgen05).
//   out = [ z_q_st (2097152) | vq_loss | indices (32768) | perplexity | usage (1024) ]
// ---------------------------------------------------------------------------

#define D_DIM   64
#define KCODES  1024
#define HW      1024
#define NPIX    32768

#define OFS_LOSS  2097152
#define OFS_IDX   2097153
#define OFS_PPL   2129921
#define OFS_USAGE 2129922

#define DELTA    1.2e-3f     // >= 2*score-err bound (7.8e-4) + margin
#define CAND_CAP 16          // per-pixel candidate cap (4 lanes x TCAP)
#define TCAP     4           // per-thread-row candidate cap

__device__ int   g_counts[KCODES];
__device__ float g_e2[KCODES];
__device__ float g_sse;
__device__ __align__(16) unsigned       g_e_bf16[KCODES * 32];  // [k][d] bf16 pairs
__device__ __align__(16) unsigned short g_cand[NPIX * CAND_CAP];
__device__ int   g_ncand[NPIX];

// ---- PTX helpers (all base-ISA: sm_75/sm_80 features) ----------------------
__device__ __forceinline__ uint32_t smem_u32(const void* p) {
    uint32_t a;
    asm("{ .reg .u64 t; cvta.to.shared.u64 t, %1; cvt.u32.u64 %0, t; }"
        : "=r"(a) : "l"(p));
    return a;
}
__device__ __forceinline__ void ldsm_x4(uint32_t& r0, uint32_t& r1,
                                        uint32_t& r2, uint32_t& r3,
                                        uint32_t addr) {
    asm volatile("ldmatrix.sync.aligned.m8n8.x4.shared.b16 {%0,%1,%2,%3}, [%4];"
                 : "=r"(r0), "=r"(r1), "=r"(r2), "=r"(r3) : "r"(addr));
}
__device__ __forceinline__ void mma_bf16(float& d0, float& d1, float& d2, float& d3,
                                         const uint32_t a[4],
                                         uint32_t b0, uint32_t b1) {
    asm volatile("mma.sync.aligned.m16n8k16.row.col.f32.bf16.bf16.f32 "
                 "{%0,%1,%2,%3}, {%4,%5,%6,%7}, {%8,%9}, {%0,%1,%2,%3};"
                 : "+f"(d0), "+f"(d1), "+f"(d2), "+f"(d3)
                 : "r"(a[0]), "r"(a[1]), "r"(a[2]), "r"(a[3]), "r"(b0), "r"(b1));
}
#define SW128(x) ((x) ^ (((x) >> 3) & 0x70))

__device__ __forceinline__ unsigned short f2bf(float x) {
    return __bfloat16_as_ushort(__float2bfloat16(x));
}

// candidate append with lazy compaction against the running threshold
__device__ __forceinline__ void cadd(float& best, float& th,
                                     float* ls, int* lk, int& cnt, bool& ovf,
                                     float s, int k) {
    if (s < best) { best = s; th = s + DELTA; }
    int m = 0;
#pragma unroll
    for (int i = 0; i < TCAP; ++i)
        if (i < cnt && ls[i] <= th) { ls[m] = ls[i]; lk[m] = lk[i]; ++m; }
    if (m < TCAP) { ls[m] = s; lk[m] = k; ++m; }
    else ovf = true;
    cnt = m;
}

// ---------------------------------------------------------------------------
// Kernel 1: codebook prep — exact sequential e2, bf16 rows, zero accumulators
// ---------------------------------------------------------------------------
__global__ void vq_prep(const float* __restrict__ cb) {
    __shared__ float cbs[32][65];
    const int tid = threadIdx.x;
    const int kb  = blockIdx.x * 32;
    for (int i = tid; i < 32 * 64; i += 256)
        cbs[i >> 6][i & 63] = cb[(size_t)kb * 64 + i];
    __syncthreads();
    if (tid < 32) {
        float s = 0.f;
#pragma unroll
        for (int d = 0; d < 64; ++d) s = fmaf(cbs[tid][d], cbs[tid][d], s);
        g_e2[kb + tid] = s;                // identical rounding to reference path
    }
    for (int i = tid; i < 32 * 32; i += 256) {
        int kk = i >> 5, j = i & 31;
        g_e_bf16[(size_t)(kb + kk) * 32 + j] =
            (unsigned)f2bf(cbs[kk][2 * j]) | ((unsigned)f2bf(cbs[kk][2 * j + 1]) << 16);
    }
    int gt = blockIdx.x * 256 + tid;
    if (gt < KCODES) g_counts[gt] = 0;
    if (gt == 0) g_sse = 0.f;
}

// ---------------------------------------------------------------------------
// Kernel 2: bf16 mma.sync scores + candidate collection
//   grid 256, 256 thr, 2 CTAs/SM. Tile: 128 px x 1024 codes.
// ---------------------------------------------------------------------------
#define A_OFF    0          // 16384 B : A bf16 [128][64] swizzled
#define STG_OFF  16384      // 33792 B : f32 z stage [64][132]   (dies after transpose)
#define B_OFF    16384      // 32768 B : B bf16 [256][64] swizzled (aliases stage)
#define E2_OFF   49152      // 4096  B : e2[1024]                (aliases stage tail)
#define NC_OFF   53248      // 512   B : ncand[128]
#define CK_OFF   53760      // 4096  B : cand[128][16] u16
#define SMEM_BYTES 57856

__global__ void __launch_bounds__(256, 2)
vq_mma(const float* __restrict__ ze) {
    extern __shared__ __align__(16) char smem[];
    const uint32_t sb = smem_u32(smem);
    const int tid  = threadIdx.x;
    const int wid  = tid >> 5;
    const int lane = tid & 31;
    const int blk  = blockIdx.x;
    const int b    = blk >> 3;
    const int hw0  = (blk & 7) * 128;

    float*          stg   = reinterpret_cast<float*>(smem + STG_OFF);
    float*          e2s   = reinterpret_cast<float*>(smem + E2_OFF);
    int*            ncand = reinterpret_cast<int*>(smem + NC_OFF);
    unsigned short* ck    = reinterpret_cast<unsigned short*>(smem + CK_OFF);

    if (tid < 128) ncand[tid] = 0;

    // ---- stage z tile (coalesced) -----------------------------------------
    const float* zbase = ze + (size_t)b * D_DIM * HW + hw0;
    for (int f = tid; f < D_DIM * 128; f += 256)
        stg[(f >> 7) * 132 + (f & 127)] = zbase[(f >> 7) * HW + (f & 127)];
    __syncthreads();

    // ---- transpose to A bf16 [p][d], SW128 --------------------------------
    if (tid < 128) {
        unsigned pk[32];
#pragma unroll
        for (int i = 0; i < 32; ++i)
            pk[i] = (unsigned)f2bf(stg[(2 * i) * 132 + tid])
                  | ((unsigned)f2bf(stg[(2 * i + 1) * 132 + tid]) << 16);
#pragma unroll
        for (int j = 0; j < 8; ++j) {
            uint32_t off = SW128((uint32_t)(tid * 128 + j * 16));
            *reinterpret_cast<uint4*>(smem + A_OFF + off) =
                make_uint4(pk[4 * j], pk[4 * j + 1], pk[4 * j + 2], pk[4 * j + 3]);
        }
    }
    __syncthreads();

    // ---- A fragments (16 px x 64 d), loaded once --------------------------
    uint32_t a[4][4];
    {
        int row = (wid << 4) + (lane & 15);
        int kb  = (lane >> 4) << 4;
#pragma unroll
        for (int ks = 0; ks < 4; ++ks) {
            uint32_t addr = sb + A_OFF + SW128((uint32_t)(row * 128 + ks * 32 + kb));
            ldsm_x4(a[ks][0], a[ks][1], a[ks][2], a[ks][3], addr);
        }
    }

    const uint32_t boffA = SW128((uint32_t)((lane & 7) * 128 + (lane >> 3) * 16));
    const uint32_t boffB = SW128((uint32_t)((lane & 7) * 128 + (lane >> 3) * 16 + 64));

    float best0 = 1e30f, th0 = 1e30f, best1 = 1e30f, th1 = 1e30f;
    float ls0[TCAP], ls1[TCAP];
    int   lk0[TCAP], lk1[TCAP];
    int   cnt0 = 0, cnt1 = 0;
    bool  ovf0 = false, ovf1 = false;

    for (int c = 0; c < 4; ++c) {
        if (c) __syncthreads();
        {   // stage 256-code B chunk
            const uint4* bsrc = reinterpret_cast<const uint4*>(g_e_bf16 + (size_t)c * 256 * 32);
#pragma unroll
            for (int i = 0; i < 8; ++i) {
                int idx = i * 256 + tid;
                *reinterpret_cast<uint4*>(smem + B_OFF + SW128((uint32_t)(idx * 16))) = bsrc[idx];
            }
            if (c == 0)
                for (int i = tid; i < KCODES; i += 256) e2s[i] = g_e2[i];
        }
        __syncthreads();

#pragma unroll 1
        for (int t = 0; t < 32; ++t) {
            uint32_t baddr = sb + B_OFF + (uint32_t)(t * 1024);
            uint32_t b0, b1, b2, b3, b4, b5, b6, b7;
            ldsm_x4(b0, b1, b2, b3, baddr + boffA);
            ldsm_x4(b4, b5, b6, b7, baddr + boffB);
            float c0 = 0.f, c1 = 0.f, c2 = 0.f, c3 = 0.f;
            mma_bf16(c0, c1, c2, c3, a[0], b0, b1);
            mma_bf16(c0, c1, c2, c3, a[1], b2, b3);
            mma_bf16(c0, c1, c2, c3, a[2], b4, b5);
            mma_bf16(c0, c1, c2, c3, a[3], b6, b7);

            const int k0 = c * 256 + t * 8 + (lane & 3) * 2;
            float2 e2v = *reinterpret_cast<const float2*>(&e2s[k0]);
            float s0 = fmaf(-2.f, c0, e2v.x);
            float s1 = fmaf(-2.f, c1, e2v.y);
            float s2 = fmaf(-2.f, c2, e2v.x);
            float s3 = fmaf(-2.f, c3, e2v.y);
            if (s0 < th0) cadd(best0, th0, ls0, lk0, cnt0, ovf0, s0, k0);
            if (s1 < th0) cadd(best0, th0, ls0, lk0, cnt0, ovf0, s1, k0 + 1);
            if (s2 < th1) cadd(best1, th1, ls1, lk1, cnt1, ovf1, s2, k0);
            if (s3 < th1) cadd(best1, th1, ls1, lk1, cnt1, ovf1, s3, k0 + 1);
        }
    }

    // ---- merge best across the 4 lanes sharing each row -------------------
    best0 = fminf(best0, __shfl_xor_sync(0xffffffffu, best0, 1));
    best0 = fminf(best0, __shfl_xor_sync(0xffffffffu, best0, 2));
    best1 = fminf(best1, __shfl_xor_sync(0xffffffffu, best1, 1));
    best1 = fminf(best1, __shfl_xor_sync(0xffffffffu, best1, 2));
    const float thm0 = best0 + DELTA, thm1 = best1 + DELTA;

    const int pl0 = (wid << 4) + (lane >> 2);
    const int pl1 = pl0 + 8;
    for (int i = 0; i < cnt0; ++i)
        if (ls0[i] <= thm0) {
            int pos = atomicAdd(&ncand[pl0], 1);
            if (pos < CAND_CAP) ck[pl0 * CAND_CAP + pos] = (unsigned short)lk0[i];
        }
    if (ovf0) atomicAdd(&ncand[pl0], 1000);
    for (int i = 0; i < cnt1; ++i)
        if (ls1[i] <= thm1) {
            int pos = atomicAdd(&ncand[pl1], 1);
            if (pos < CAND_CAP) ck[pl1 * CAND_CAP + pos] = (unsigned short)lk1[i];
        }
    if (ovf1) atomicAdd(&ncand[pl1], 1000);
    __syncthreads();

    if (tid < 128) {
        int p = blk * 128 + tid;
        g_ncand[p] = ncand[tid];
        const uint4* src = reinterpret_cast<const uint4*>(&ck[tid * CAND_CAP]);
        uint4* dst = reinterpret_cast<uint4*>(&g_cand[(size_t)p * CAND_CAP]);
        dst[0] = src[0];
        dst[1] = src[1];
    }
}

// ---------------------------------------------------------------------------
// Kernel 3: exact rescore (replicates Round-0 passing rounding), outputs
// ---------------------------------------------------------------------------
__global__ void __launch_bounds__(256)
vq_rescore(const float* __restrict__ ze, const float* __restrict__ cb,
           float* __restrict__ out) {
    __shared__ int hist[KCODES];
    const int tid = threadIdx.x;
    for (int i = tid; i < KCODES; i += 256) hist[i] = 0;
    __syncthreads();

    const int p  = blockIdx.x * 256 + tid;
    const int b  = p >> 10;
    const int hw = p & 1023;
    const float* zp = ze + (size_t)b * D_DIM * HW + hw;

    float z[D_DIM];
#pragma unroll
    for (int d = 0; d < D_DIM; ++d) z[d] = zp[d * HW];
    float z2 = 0.f;
#pragma unroll
    for (int d = 0; d < D_DIM; ++d) z2 = fmaf(z[d], z[d], z2);

    int   n  = g_ncand[p];
    int   bi = 0x7fffffff;
    float bd = 3.4e38f;

    if (n == 1) {
        bi = g_cand[(size_t)p * CAND_CAP];
    } else if (n <= CAND_CAP) {
        for (int i = 0; i < n; ++i) {
            int k = g_cand[(size_t)p * CAND_CAP + i];
            const float4* er = reinterpret_cast<const float4*>(cb + (size_t)k * D_DIM);
            float dot = 0.f;
#pragma unroll
            for (int q = 0; q < 16; ++q) {
                float4 v = er[q];
                dot = fmaf(z[q * 4 + 0], v.x, dot);
                dot = fmaf(z[q * 4 + 1], v.y, dot);
                dot = fmaf(z[q * 4 + 2], v.z, dot);
                dot = fmaf(z[q * 4 + 3], v.w, dot);
            }
            float dist = fmaf(-2.f, dot, z2 + g_e2[k]);
            if (dist < bd || (dist == bd && k < bi)) { bd = dist; bi = k; }
        }
    } else {  // overflow fallback: exact full scan
        for (int k = 0; k < KCODES; ++k) {
            const float4* er = reinterpret_cast<const float4*>(cb + (size_t)k * D_DIM);
            float dot = 0.f;
#pragma unroll
            for (int q = 0; q < 16; ++q) {
                float4 v = er[q];
                dot = fmaf(z[q * 4 + 0], v.x, dot);
                dot = fmaf(z[q * 4 + 1], v.y, dot);
                dot = fmaf(z[q * 4 + 2], v.z, dot);
                dot = fmaf(z[q * 4 + 3], v.w, dot);
            }
            float dist = fmaf(-2.f, dot, z2 + g_e2[k]);
            if (dist < bd) { bd = dist; bi = k; }
        }
    }

    out[OFS_IDX + p] = (float)bi;
    atomicAdd(&hist[bi], 1);

    const float4* er = reinterpret_cast<const float4*>(cb + (size_t)bi * D_DIM);
    float* zo = out + (size_t)b * D_DIM * HW + hw;
    float sse = 0.f;
#pragma unroll
    for (int q = 0; q < 16; ++q) {
        float4 v = er[q];
        float vv[4] = {v.x, v.y, v.z, v.w};
#pragma unroll
        for (int c = 0; c < 4; ++c) {
            int d = q * 4 + c;
            float diff = vv[c] - z[d];     // fl(z_q - z_e)
            sse = fmaf(diff, diff, sse);
            zo[d * HW] = z[d] + diff;      // fl(z_e + fl(z_q - z_e))
        }
    }
#pragma unroll
    for (int o = 16; o; o >>= 1) sse += __shfl_xor_sync(0xffffffffu, sse, o);
    if ((tid & 31) == 0) atomicAdd(&g_sse, sse);

    __syncthreads();
    for (int i = tid; i < KCODES; i += 256) {
        int c = hist[i];
        if (c) atomicAdd(&g_counts[i], c);
    }
}

// ---------------------------------------------------------------------------
// Kernel 4: finalize — usage, perplexity, vq_loss
// ---------------------------------------------------------------------------
__global__ void vq_final(float* __restrict__ out) {
    __shared__ float red[32];
    int t = threadIdx.x;
    float u = (float)g_counts[t] / 32768.0f;
    out[OFS_USAGE + t] = u;
    float h = u * logf(u + 1e-10f);
#pragma unroll
    for (int o = 16; o; o >>= 1) h += __shfl_xor_sync(0xffffffffu, h, o);
    if ((t & 31) == 0) red[t >> 5] = h;
    __syncthreads();
    if (t < 32) {
        float v = red[t];
#pragma unroll
        for (int o = 16; o; o >>= 1) v += __shfl_xor_sync(0xffffffffu, v, o);
        if (t == 0) {
            out[OFS_PPL] = expf(-v);
            float m = g_sse / 2097152.0f;
            out[OFS_LOSS] = m + 0.25f * m;
        }
    }
}

// ---------------------------------------------------------------------------
extern "C" void kernel_launch(void* const* d_in, const int* in_sizes, int n_in,
                              void* d_out, int out_size) {
    const float* a0 = (const float*)d_in[0];
    const float* a1 = (const float*)d_in[1];
    const float* ze = a0;
    const float* cb = a1;
    if (n_in >= 2 && in_sizes[0] == KCODES * D_DIM) { ze = a1; cb = a0; }
    float* out = (float*)d_out;

    cudaFuncSetAttribute(vq_mma, cudaFuncAttributeMaxDynamicSharedMemorySize,
                         SMEM_BYTES);

    vq_prep<<<32, 256>>>(cb);
    vq_mma<<<256, 256, SMEM_BYTES>>>(ze);
    vq_rescore<<<128, 256>>>(ze, cb, out);
    vq_final<<<1, 1024>>>(out);
}

// round 4
// speedup vs baseline: 4.6744x; 4.6744x over previous
#include <cuda_runtime.h>
#include <math.h>
#include <stdint.h>

// ---------------------------------------------------------------------------
// VQ-VAE VectorQuantizer forward — exact fp32 via packed f32x2 FMA (sm_100
// base ISA; tensor paths unavailable in this toolchain: tcgen05 won't
// assemble, legacy mma.sync is emulated ~6x slower).
//   out = [ z_q_st (2097152) | vq_loss | indices (32768) | perplexity | usage (1024) ]
// ---------------------------------------------------------------------------

#define D_DIM   64
#define KCODES  1024
#define HW      1024
#define TM      128            // pixels per CTA tile
#define KC      64             // codes per chunk
#define NCHUNK  (KCODES / KC)  // 16
#define NTILES  256

#define OFS_LOSS  2097152
#define OFS_IDX   2097153
#define OFS_PPL   2129921
#define OFS_USAGE 2129922

__device__ int   g_counts[KCODES];
__device__ float g_e2[KCODES];
__device__ float g_sse;
__device__ __align__(16) float g_eT[D_DIM * KCODES];   // codebook transposed [d][k]

// ---- packed f32x2 helpers --------------------------------------------------
__device__ __forceinline__ unsigned long long pack2(float x, float y) {
    unsigned long long r;
    asm("mov.b64 %0, {%1, %2};" : "=l"(r) : "f"(x), "f"(y));
    return r;
}
__device__ __forceinline__ void fma2(unsigned long long& d,
                                     unsigned long long a,
                                     unsigned long long b) {
    asm("fma.rn.f32x2 %0, %1, %2, %0;" : "+l"(d) : "l"(a), "l"(b));
}
__device__ __forceinline__ float2 unpack2(unsigned long long v) {
    float2 f;
    asm("mov.b64 {%0, %1}, %2;" : "=f"(f.x), "=f"(f.y) : "l"(v));
    return f;
}

// ---------------------------------------------------------------------------
// Kernel 1: prep — exact sequential e2, transposed codebook, zero accumulators
// ---------------------------------------------------------------------------
__global__ void vq_prep(const float* __restrict__ cb) {
    __shared__ float cbs[32][65];
    const int tid = threadIdx.x;
    const int kb  = blockIdx.x * 32;
    for (int i = tid; i < 32 * 64; i += 256)
        cbs[i >> 6][i & 63] = cb[(size_t)kb * 64 + i];
    __syncthreads();
    if (tid < 32) {                    // identical rounding to reference path
        float s = 0.f;
#pragma unroll
        for (int d = 0; d < 64; ++d) s = fmaf(cbs[tid][d], cbs[tid][d], s);
        g_e2[kb + tid] = s;
    }
    {   // transposed write g_eT[d][k]; conflict-free smem reads
        int d = tid >> 2, q = tid & 3;
        float* dst = g_eT + (size_t)d * KCODES + kb + q * 8;
#pragma unroll
        for (int j = 0; j < 8; ++j) dst[j] = cbs[q * 8 + j][d];
    }
    int gt = blockIdx.x * 256 + tid;
    if (gt < KCODES) g_counts[gt] = 0;
    if (gt == 0) g_sse = 0.f;
}

// ---------------------------------------------------------------------------
// Kernel 2: main — f32x2 distances (pixel-pair packed), argmin, gather, stats
//   grid 256, 256 thr, 2 CTAs/SM. Thread tile: 8 px (4 pairs) x 4 codes.
// ---------------------------------------------------------------------------
struct SmemMain {
    float z_s[D_DIM][TM + 4];     // 33792 B : z tile [d][p]
    float e_s[D_DIM][KC + 4];     // 17408 B : codebook chunk [d][k]
    float e2s[KCODES];            //  4096 B
    float z2_s[TM];               //   512 B
    float red_d[16][TM];          //  8192 B
    int   red_i[16][TM];          //  8192 B
    int   idx_s[TM];              //   512 B
    int   cnt_s[KCODES];          //  4096 B
};                                // 76800 B total -> 2 CTAs/SM

__global__ void __launch_bounds__(256, 2)
vq_main(const float* __restrict__ ze, const float* __restrict__ cb,
        float* __restrict__ out) {
    extern __shared__ __align__(16) char smem_raw[];
    SmemMain* sm = reinterpret_cast<SmemMain*>(smem_raw);

    const int tid  = threadIdx.x;
    const int tile = blockIdx.x;
    const int b    = tile >> 3;
    const int hw0  = (tile & 7) * TM;
    const float* zbase = ze + (size_t)b * D_DIM * HW + hw0;

    for (int i = tid; i < KCODES; i += 256) sm->cnt_s[i] = 0;
    for (int i = tid; i < KCODES; i += 256) sm->e2s[i] = g_e2[i];
    for (int f = tid; f < D_DIM * TM; f += 256) {
        int d = f >> 7, p = f & 127;
        sm->z_s[d][p] = zbase[d * HW + p];
    }
    __syncthreads();

    // per-pixel squared norm, sequential fmaf (reference rounding)
    if (tid < TM) {
        float s = 0.f;
#pragma unroll
        for (int d = 0; d < D_DIM; ++d) s = fmaf(sm->z_s[d][tid], sm->z_s[d][tid], s);
        sm->z2_s[tid] = s;
    }
    __syncthreads();

    const int pcol  = tid & 15;
    const int krow  = tid >> 4;
    const int p0    = pcol * 8;
    const int kloc0 = krow * 4;

    float z2r[8];
#pragma unroll
    for (int j = 0; j < 8; ++j) z2r[j] = sm->z2_s[p0 + j];

    float bestd[8];
    int   besti[8];
#pragma unroll
    for (int j = 0; j < 8; ++j) { bestd[j] = 3.4e38f; besti[j] = 0; }

    const int d_st = tid >> 2, q_st = tid & 3;   // staging roles

    for (int c = 0; c < NCHUNK; ++c) {
        const int kb = c * KC;
        if (c) __syncthreads();                  // previous chunk's e_s reads done

        // ---- stage codebook chunk (straight coalesced copy of g_eT slice) --
        {
            const float4* src = reinterpret_cast<const float4*>(
                                    g_eT + (size_t)d_st * KCODES + kb + q_st * 16);
            float4 v0 = src[0], v1 = src[1], v2 = src[2], v3 = src[3];
            float4* dst = reinterpret_cast<float4*>(&sm->e_s[d_st][q_st * 16]);
            dst[0] = v0; dst[1] = v1; dst[2] = v2; dst[3] = v3;
        }
        __syncthreads();

        // ---- accumulate dots: 4 px-pairs x 4 codes, z pairs load packed ----
        unsigned long long acc[4][4];
#pragma unroll
        for (int jp = 0; jp < 4; ++jp)
#pragma unroll
            for (int j = 0; j < 4; ++j) acc[jp][j] = 0ull;

#pragma unroll 16
        for (int d = 0; d < D_DIM; ++d) {
            ulonglong2 zA = *reinterpret_cast<const ulonglong2*>(&sm->z_s[d][p0]);
            ulonglong2 zB = *reinterpret_cast<const ulonglong2*>(&sm->z_s[d][p0 + 4]);
            float4 ev = *reinterpret_cast<const float4*>(&sm->e_s[d][kloc0]);
            unsigned long long e0 = pack2(ev.x, ev.x);
            unsigned long long e1 = pack2(ev.y, ev.y);
            unsigned long long e2p = pack2(ev.z, ev.z);
            unsigned long long e3 = pack2(ev.w, ev.w);
            fma2(acc[0][0], zA.x, e0); fma2(acc[0][1], zA.x, e1);
            fma2(acc[0][2], zA.x, e2p); fma2(acc[0][3], zA.x, e3);
            fma2(acc[1][0], zA.y, e0); fma2(acc[1][1], zA.y, e1);
            fma2(acc[1][2], zA.y, e2p); fma2(acc[1][3], zA.y, e3);
            fma2(acc[2][0], zB.x, e0); fma2(acc[2][1], zB.x, e1);
            fma2(acc[2][2], zB.x, e2p); fma2(acc[2][3], zB.x, e3);
            fma2(acc[3][0], zB.y, e0); fma2(acc[3][1], zB.y, e1);
            fma2(acc[3][2], zB.y, e2p); fma2(acc[3][3], zB.y, e3);
        }

        // ---- epilogue: exact reference rounding, strict-< keeps first min --
        float4 e2v = *reinterpret_cast<const float4*>(&sm->e2s[kb + kloc0]);
        const float e2a[4] = {e2v.x, e2v.y, e2v.z, e2v.w};
#pragma unroll
        for (int jp = 0; jp < 4; ++jp) {
            const int px0 = 2 * jp, px1 = px0 + 1;
#pragma unroll
            for (int j = 0; j < 4; ++j) {
                float2 s = unpack2(acc[jp][j]);
                const int k = kb + kloc0 + j;
                float d0 = fmaf(-2.f, s.x, z2r[px0] + e2a[j]);
                float d1 = fmaf(-2.f, s.y, z2r[px1] + e2a[j]);
                if (d0 < bestd[px0]) { bestd[px0] = d0; besti[px0] = k; }
                if (d1 < bestd[px1]) { bestd[px1] = d1; besti[px1] = k; }
            }
        }
    }

    // ---- cross-thread argmin over the 16 krows, lexicographic (dist, k) ----
#pragma unroll
    for (int j = 0; j < 8; ++j) {
        sm->red_d[krow][p0 + j] = bestd[j];
        sm->red_i[krow][p0 + j] = besti[j];
    }
    __syncthreads();

    if (tid < TM) {
        float bd = sm->red_d[0][tid];
        int   bi = sm->red_i[0][tid];
#pragma unroll
        for (int r = 1; r < 16; ++r) {
            float d2 = sm->red_d[r][tid];
            int   i2 = sm->red_i[r][tid];
            if (d2 < bd || (d2 == bd && i2 < bi)) { bd = d2; bi = i2; }
        }
        sm->idx_s[tid] = bi;
        out[OFS_IDX + tile * TM + tid] = (float)bi;
        atomicAdd(&sm->cnt_s[bi], 1);
    }
    __syncthreads();

    // flush histogram
    for (int i = tid; i < KCODES; i += 256) {
        int cnum = sm->cnt_s[i];
        if (cnum) atomicAdd(&g_counts[i], cnum);
    }

    // ---- gather z_q, z_q_st with reference's two roundings, SSE, store ----
    if (tid < TM) {
        const int p  = tid;
        const int bi = sm->idx_s[p];
        const float4* er = reinterpret_cast<const float4*>(cb + (size_t)bi * D_DIM);
        float* zo = out + (size_t)b * D_DIM * HW + hw0 + p;
        float sse = 0.f;
#pragma unroll
        for (int q = 0; q < 16; ++q) {
            float4 v = er[q];
            float vv[4] = {v.x, v.y, v.z, v.w};
#pragma unroll
            for (int cc = 0; cc < 4; ++cc) {
                int d = q * 4 + cc;
                float zev  = sm->z_s[d][p];
                float diff = vv[cc] - zev;       // fl(z_q - z_e)
                sse = fmaf(diff, diff, sse);
                zo[d * HW] = zev + diff;         // fl(z_e + fl(z_q - z_e))
            }
        }
#pragma unroll
        for (int o = 16; o; o >>= 1) sse += __shfl_xor_sync(0xffffffffu, sse, o);
        if ((tid & 31) == 0) atomicAdd(&g_sse, sse);
    }
}

// ---------------------------------------------------------------------------
// Kernel 3: finalize — usage, perplexity, vq_loss
// ---------------------------------------------------------------------------
__global__ void vq_final(float* __restrict__ out) {
    __shared__ float red[32];
    int t = threadIdx.x;
    float u = (float)g_counts[t] / 32768.0f;
    out[OFS_USAGE + t] = u;
    float h = u * logf(u + 1e-10f);
#pragma unroll
    for (int o = 16; o; o >>= 1) h += __shfl_xor_sync(0xffffffffu, h, o);
    if ((t & 31) == 0) red[t >> 5] = h;
    __syncthreads();
    if (t < 32) {
        float v = red[t];
#pragma unroll
        for (int o = 16; o; o >>= 1) v += __shfl_xor_sync(0xffffffffu, v, o);
        if (t == 0) {
            out[OFS_PPL] = expf(-v);
            float m = g_sse / 2097152.0f;
            out[OFS_LOSS] = m + 0.25f * m;
        }
    }
}

// ---------------------------------------------------------------------------
extern "C" void kernel_launch(void* const* d_in, const int* in_sizes, int n_in,
                              void* d_out, int out_size) {
    const float* a0 = (const float*)d_in[0];
    const float* a1 = (const float*)d_in[1];
    const float* ze = a0;
    const float* cb = a1;
    if (n_in >= 2 && in_sizes[0] == KCODES * D_DIM) { ze = a1; cb = a0; }
    float* out = (float*)d_out;

    static_assert(sizeof(SmemMain) <= 100 * 1024, "smem too big");
    cudaFuncSetAttribute(vq_main, cudaFuncAttributeMaxDynamicSharedMemorySize,
                         (int)sizeof(SmemMain));

    vq_prep<<<32, 256>>>(cb);
    vq_main<<<NTILES, 256, sizeof(SmemMain)>>>(ze, cb, out);
    vq_final<<<1, 1024>>>(out);
}